// round 7
// baseline (speedup 1.0000x reference)
#include <cuda_runtime.h>
#include <cstdint>
#include <cstddef>

#define NN    50000
#define BB    64
#define DD    16
#define NDRVN 1000
#define MAXACT (NDRVN * DD)

typedef unsigned long long u64;

struct Params { const float* w[7]; const float* b[7]; };

// Scratch (static device arrays are the sanctioned workaround)
__device__ float g_bufA[(size_t)NN * BB];
__device__ float g_bufB[(size_t)NN * BB];
__device__ unsigned char g_flags[NN];
__device__ int g_list[MAXACT];
__device__ int g_cnt;

// ---------------- packed f32x2 primitives (Blackwell FFMA2 path) ----------------
__device__ __forceinline__ u64 fma2(u64 a, u64 b, u64 c) {
    u64 d;
    asm("fma.rn.f32x2 %0, %1, %2, %3;" : "=l"(d) : "l"(a), "l"(b), "l"(c));
    return d;
}
__device__ __forceinline__ u64 add2(u64 a, u64 b) {
    u64 d;
    asm("add.rn.f32x2 %0, %1, %2;" : "=l"(d) : "l"(a), "l"(b));
    return d;
}
__device__ __forceinline__ u64 mul2(u64 a, u64 b) {
    u64 d;
    asm("mul.rn.f32x2 %0, %1, %2;" : "=l"(d) : "l"(a), "l"(b));
    return d;
}
__device__ __forceinline__ u64 relu2(u64 x) {
    u64 r;
    asm("{\n\t"
        ".reg .f32 lo, hi;\n\t"
        "mov.b64 {lo, hi}, %1;\n\t"
        "max.f32 lo, lo, 0f00000000;\n\t"
        "max.f32 hi, hi, 0f00000000;\n\t"
        "mov.b64 %0, {lo, hi};\n\t"
        "}" : "=l"(r) : "l"(x));
    return r;
}

// ---------------- shared weights: duplicated (w,w) pairs, bias folded in ----------------
// s_w[l][co][q] as ulonglong2 (LDS.128 = 2 weight-pairs). Row of 16 duplicated floats:
//   layers 1..6: slots 0..14 = weights (ci*3+k), slot 15 = bias
//   layer  0   : slots 0..2  = weights, slot 3 = bias
__device__ __forceinline__ void load_weights(const Params& p, ulonglong2 (*sw)[5][8]) {
    float2* fp = (float2*)sw;
    for (int e = threadIdx.x; e < 7 * 5 * 16; e += blockDim.x) {
        int l = e / 80;
        int r = e % 80;
        int co = r / 16;
        int j  = r % 16;
        int nci   = (l == 0) ? 1 : 5;
        int nco   = (l == 6) ? 1 : 5;
        int nw    = nci * 3;
        int bslot = (l == 0) ? 3 : 15;
        float v = 0.0f;
        if (co < nco) {
            if (j < nw)          v = p.w[l][co * nw + j];
            else if (j == bslot) v = p.b[l][co];
        }
        fp[e] = make_float2(v, v);
    }
    __syncthreads();
}

// ---------------- streaming 7-layer conv: one node per warp, batch-pair per lane ----------------
__device__ __forceinline__ u64 node_forward(const float* __restrict__ zin,
                                            const int* __restrict__ nbr_row,
                                            int lane,
                                            const ulonglong2 (*sw)[5][8]) {
    // 16 neighbor indices via broadcast int4 loads
    int4 i4[4];
#pragma unroll
    for (int q = 0; q < 4; q++) i4[q] = ((const int4*)nbr_row)[q];
    int idx[16] = {i4[0].x, i4[0].y, i4[0].z, i4[0].w,
                   i4[1].x, i4[1].y, i4[1].z, i4[1].w,
                   i4[2].x, i4[2].y, i4[2].z, i4[2].w,
                   i4[3].x, i4[3].y, i4[3].z, i4[3].w};

    // Gather burst: z is (N, B) so one neighbor = 64 contiguous floats; lane reads its pair (LDG.64)
    u64 in[16];
#pragma unroll
    for (int j = 0; j < 16; j++)
        in[j] = *(const u64*)(zin + ((size_t)(unsigned)idx[j] << 6) + 2 * lane);

    u64 iw0 = 0, iw1 = 0;       // input 2-deep window
    u64 win[6][2][5];           // 2-deep windows of layer-0..5 outputs
#pragma unroll
    for (int a = 0; a < 6; a++)
#pragma unroll
        for (int bq = 0; bq < 2; bq++)
#pragma unroll
            for (int c = 0; c < 5; c++) win[a][bq][c] = 0;

    u64 o14 = 0, o15 = 0;

#pragma unroll
    for (int t = 0; t < 16; t++) {
        u64 x = in[t];
        u64 prev[5];
#pragma unroll
        for (int c = 0; c < 5; c++) prev[c] = 0;

        // layer 0: 1 -> 5, active for t >= 2 (t compile-time: fully unrolled)
        if (t >= 2) {
#pragma unroll
            for (int co = 0; co < 5; co++) {
                ulonglong2 q0 = sw[0][co][0];
                ulonglong2 q1 = sw[0][co][1];
                u64 acc = q1.y;            // bias
                acc = fma2(iw0, q0.x, acc);
                acc = fma2(iw1, q0.y, acc);
                acc = fma2(x,   q1.x, acc);
                prev[co] = relu2(acc);
            }
        }
        iw0 = iw1; iw1 = x;

#pragma unroll
        for (int l = 1; l <= 6; l++) {
            u64 nc[5];
#pragma unroll
            for (int c = 0; c < 5; c++) nc[c] = 0;

            if (t >= 2 * (l + 1)) {
                u64 v[15];
#pragma unroll
                for (int ci = 0; ci < 5; ci++) {
                    v[3 * ci + 0] = win[l - 1][0][ci];
                    v[3 * ci + 1] = win[l - 1][1][ci];
                    v[3 * ci + 2] = prev[ci];
                }
                const int nco = (l == 6) ? 1 : 5;
#pragma unroll
                for (int co = 0; co < nco; co++) {
                    ulonglong2 q7 = sw[l][co][7];   // (slot14, bias)
                    // dual accumulator chains: acc0 = bias + slots 0..7, acc1 = slots 8..14
                    u64 acc0 = q7.y;
#pragma unroll
                    for (int q = 0; q < 4; q++) {
                        ulonglong2 ww = sw[l][co][q];
                        acc0 = fma2(v[2 * q],     ww.x, acc0);
                        acc0 = fma2(v[2 * q + 1], ww.y, acc0);
                    }
                    u64 acc1 = mul2(v[14], q7.x);   // slot 14
#pragma unroll
                    for (int q = 4; q < 7; q++) {
                        ulonglong2 ww = sw[l][co][q];
                        acc1 = fma2(v[2 * q],     ww.x, acc1);
                        acc1 = fma2(v[2 * q + 1], ww.y, acc1);
                    }
                    nc[co] = relu2(add2(acc0, acc1));
                }
            }
            if (t >= 2 * l) {
#pragma unroll
                for (int ci = 0; ci < 5; ci++) {
                    win[l - 1][0][ci] = win[l - 1][1][ci];
                    win[l - 1][1][ci] = prev[ci];
                }
            }
            if (t >= 2 * (l + 1)) {
#pragma unroll
                for (int c = 0; c < 5; c++) prev[c] = nc[c];
            }
            if (l == 6) {
                if (t == 14) o14 = nc[0];
                if (t == 15) o15 = nc[0];
            }
        }
    }
    const u64 HALF2 = 0x3F0000003F000000ULL;  // {0.5f, 0.5f}
    return mul2(add2(o14, o15), HALF2);
}

// ---------------- kernels ----------------
__global__ void __launch_bounds__(128) transpose_kernel(const float* __restrict__ x,
                                                        float* __restrict__ zt) {
    int n  = blockIdx.x * blockDim.x + threadIdx.x;
    int bp = blockIdx.y;  // batch pair 0..31
    if (n >= NN) return;
    float lo = x[(size_t)(2 * bp) * NN + n];
    float hi = x[(size_t)(2 * bp + 1) * NN + n];
    *(float2*)(zt + (size_t)n * BB + 2 * bp) = make_float2(lo, hi);
}

__global__ void clear_flags_kernel(unsigned char* f, int* cnt) {
    int i = blockIdx.x * blockDim.x + threadIdx.x;
    if (i < NN) f[i] = 0;
    if (i == 0) *cnt = 0;
}

__global__ void mark_flags_kernel(const int* __restrict__ drv,
                                  const int* __restrict__ nbr,
                                  unsigned char* f) {
    int i = blockIdx.x * blockDim.x + threadIdx.x;
    if (i < NDRVN * DD) {
        int d = drv[i >> 4];
        f[nbr[d * DD + (i & 15)]] = 1;
    }
}

__global__ void compact_kernel(const unsigned char* __restrict__ f,
                               int* __restrict__ list, int* __restrict__ cnt) {
    int i = blockIdx.x * blockDim.x + threadIdx.x;
    if (i < NN && f[i]) {
        int pos = atomicAdd(cnt, 1);
        list[pos] = i;
    }
}

__global__ void __launch_bounds__(128) pass_kernel(const float* __restrict__ zin,
                                                   float* __restrict__ zout,
                                                   const int* __restrict__ nbr,
                                                   Params p) {
    __shared__ ulonglong2 s_w[7][5][8];
    load_weights(p, s_w);
    int warp = threadIdx.x >> 5;
    int lane = threadIdx.x & 31;
    int node = blockIdx.x * 4 + warp;
    if (node >= NN) return;
    u64 r = node_forward(zin, nbr + node * DD, lane, s_w);
    *(u64*)(zout + (size_t)node * BB + 2 * lane) = r;
}

__global__ void __launch_bounds__(128) pass_list_kernel(const float* __restrict__ zin,
                                                        float* __restrict__ zout,
                                                        const int* __restrict__ nbr,
                                                        const int* __restrict__ list,
                                                        const int* __restrict__ cnt,
                                                        Params p) {
    __shared__ ulonglong2 s_w[7][5][8];
    load_weights(p, s_w);
    int warp = threadIdx.x >> 5;
    int lane = threadIdx.x & 31;
    int i = blockIdx.x * 4 + warp;
    if (i >= *cnt) return;
    int node = list[i];
    u64 r = node_forward(zin, nbr + node * DD, lane, s_w);
    *(u64*)(zout + (size_t)node * BB + 2 * lane) = r;
}

__global__ void __launch_bounds__(128) driver_kernel(const float* __restrict__ zin,
                                                     const int* __restrict__ nbr,
                                                     const int* __restrict__ drv,
                                                     float* __restrict__ out,
                                                     Params p) {
    __shared__ ulonglong2 s_w[7][5][8];
    load_weights(p, s_w);
    int warp = threadIdx.x >> 5;
    int lane = threadIdx.x & 31;
    int i = blockIdx.x * 4 + warp;
    if (i >= NDRVN) return;
    int node = drv[i];
    u64 r = node_forward(zin, nbr + node * DD, lane, s_w);
    float lo, hi;
    asm("mov.b64 {%0, %1}, %2;" : "=f"(lo), "=f"(hi) : "l"(r));
    out[(size_t)(2 * lane) * NDRVN + i]     = lo;
    out[(size_t)(2 * lane + 1) * NDRVN + i] = hi;
}

// ---------------- launch ----------------
extern "C" void kernel_launch(void* const* d_in, const int* in_sizes, int n_in,
                              void* d_out, int out_size) {
    const float* x   = (const float*)d_in[0];
    const int*   nbr = (const int*)d_in[1];
    const int*   drv = (const int*)d_in[2];
    Params p;
    for (int l = 0; l < 7; l++) {
        p.w[l] = (const float*)d_in[3 + 2 * l];
        p.b[l] = (const float*)d_in[4 + 2 * l];
    }

    float* A; float* B; unsigned char* fl; int* lst; int* cnt;
    cudaGetSymbolAddress((void**)&A,   g_bufA);
    cudaGetSymbolAddress((void**)&B,   g_bufB);
    cudaGetSymbolAddress((void**)&fl,  g_flags);
    cudaGetSymbolAddress((void**)&lst, g_list);
    cudaGetSymbolAddress((void**)&cnt, g_cnt);

    const int blocks_full = (NN + 3) / 4;
    const int blocks_list = (MAXACT + 3) / 4;

    // transpose z0 to (N, B)
    transpose_kernel<<<dim3((NN + 127) / 128, BB / 2), 128>>>(x, A);
    // active-set flags for pass 3
    clear_flags_kernel<<<(NN + 255) / 256, 256>>>(fl, cnt);
    mark_flags_kernel<<<(NDRVN * DD + 255) / 256, 256>>>(drv, nbr, fl);
    // pass 1 (full)
    pass_kernel<<<blocks_full, 128>>>(A, B, nbr, p);
    // compact flags into list
    compact_kernel<<<(NN + 255) / 256, 256>>>(fl, lst, cnt);
    // pass 2 (full)
    pass_kernel<<<blocks_full, 128>>>(B, A, nbr, p);
    // pass 3 (compacted active set, <=16000 nodes)
    pass_list_kernel<<<blocks_list, 128>>>(A, B, nbr, lst, cnt, p);
    // pass 4 (drivers only, straight to output)
    driver_kernel<<<(NDRVN + 3) / 4, 128>>>(B, nbr, drv, (float*)d_out, p);
}

// round 8
// speedup vs baseline: 12.0365x; 12.0365x over previous
#include <cuda_runtime.h>
#include <cstdint>
#include <cstddef>

#define NN    50000
#define BB    64
#define DD    16
#define NDRVN 1000
#define MAXACT (NDRVN * DD)

typedef unsigned long long u64;

struct Params { const float* w[7]; const float* b[7]; };

// Scratch (static device arrays are the sanctioned workaround)
__device__ float g_bufA[(size_t)NN * BB];
__device__ float g_bufB[(size_t)NN * BB];
__device__ unsigned char g_flags[NN];
__device__ int g_list[MAXACT];
__device__ int g_cnt;

// ---------------- packed f32x2 primitives (Blackwell FFMA2 path) ----------------
__device__ __forceinline__ u64 fma2(u64 a, u64 b, u64 c) {
    u64 d;
    asm("fma.rn.f32x2 %0, %1, %2, %3;" : "=l"(d) : "l"(a), "l"(b), "l"(c));
    return d;
}
__device__ __forceinline__ u64 add2(u64 a, u64 b) {
    u64 d;
    asm("add.rn.f32x2 %0, %1, %2;" : "=l"(d) : "l"(a), "l"(b));
    return d;
}
__device__ __forceinline__ u64 mul2(u64 a, u64 b) {
    u64 d;
    asm("mul.rn.f32x2 %0, %1, %2;" : "=l"(d) : "l"(a), "l"(b));
    return d;
}
__device__ __forceinline__ u64 relu2(u64 x) {
    u64 r;
    asm("{\n\t"
        ".reg .f32 lo, hi;\n\t"
        "mov.b64 {lo, hi}, %1;\n\t"
        "max.f32 lo, lo, 0f00000000;\n\t"
        "max.f32 hi, hi, 0f00000000;\n\t"
        "mov.b64 %0, {lo, hi};\n\t"
        "}" : "=l"(r) : "l"(x));
    return r;
}

// ---------------- shared weights: duplicated (w,w) pairs, bias folded in ----------------
// s_w[l][co][q] as ulonglong2 (LDS.128 = 2 weight-pairs). Row of 16 duplicated floats:
//   layers 1..6: slots 0..14 = weights (ci*3+k), slot 15 = bias
//   layer  0   : slots 0..2  = weights, slot 3 = bias
__device__ __forceinline__ void load_weights(const Params& p, ulonglong2 (*sw)[5][8]) {
    float2* fp = (float2*)sw;
    for (int e = threadIdx.x; e < 7 * 5 * 16; e += blockDim.x) {
        int l = e / 80;
        int r = e % 80;
        int co = r / 16;
        int j  = r % 16;
        int nci   = (l == 0) ? 1 : 5;
        int nco   = (l == 6) ? 1 : 5;
        int nw    = nci * 3;
        int bslot = (l == 0) ? 3 : 15;
        float v = 0.0f;
        if (co < nco) {
            if (j < nw)          v = p.w[l][co * nw + j];
            else if (j == bslot) v = p.b[l][co];
        }
        fp[e] = make_float2(v, v);
    }
    __syncthreads();
}

// ---------------- layer-major streaming conv: one node per warp, batch-pair per lane ----
// Sequence kept in registers, processed layer-by-layer in place; weights register-cached
// per (layer, co, half-octet) and reused across a 4-wide t-chunk (3.8x fewer LDS).
__device__ __forceinline__ u64 node_forward(const float* __restrict__ zin,
                                            const int* __restrict__ nbr_row,
                                            int lane,
                                            const ulonglong2 (*sw)[5][8]) {
    // 16 neighbor indices via broadcast int4 loads
    int4 i4[4];
#pragma unroll
    for (int q = 0; q < 4; q++) i4[q] = ((const int4*)nbr_row)[q];
    int idx[16] = {i4[0].x, i4[0].y, i4[0].z, i4[0].w,
                   i4[1].x, i4[1].y, i4[1].z, i4[1].w,
                   i4[2].x, i4[2].y, i4[2].z, i4[2].w,
                   i4[3].x, i4[3].y, i4[3].z, i4[3].w};

    // Gather burst: z is (N, B) so one neighbor = 64 contiguous floats; lane reads its pair (LDG.64)
    u64 in[16];
#pragma unroll
    for (int j = 0; j < 16; j++)
        in[j] = *(const u64*)(zin + ((size_t)(unsigned)idx[j] << 6) + 2 * lane);

    u64 s[5][14];   // in-register sequence, overwritten in place layer by layer

    // ---- layer 0: 1 -> 5 channels, 16 -> 14 wide (weights held in regs across all t) ----
#pragma unroll
    for (int co = 0; co < 5; co++) {
        ulonglong2 q0 = sw[0][co][0];   // (w0, w1)
        ulonglong2 q1 = sw[0][co][1];   // (w2, bias)
#pragma unroll
        for (int t = 0; t < 14; t++) {
            u64 acc = q1.y;
            acc = fma2(in[t],     q0.x, acc);
            acc = fma2(in[t + 1], q0.y, acc);
            acc = fma2(in[t + 2], q1.x, acc);
            s[co][t] = relu2(acc);
        }
    }

    // ---- layers 1..6: 5 -> 5 (or 1), in place, t-chunks of 4 ----
#pragma unroll
    for (int l = 1; l <= 6; l++) {
        const int Lo  = 14 - 2 * l;          // output length this layer
        const int nco = (l == 6) ? 1 : 5;
#pragma unroll
        for (int c0 = 0; c0 < Lo; c0 += 4) {
            const int CL = (Lo - c0 < 4) ? (Lo - c0) : 4;
            u64 out[5][4];
#pragma unroll
            for (int co = 0; co < 5; co++) {
                if (co < nco) {
                    u64 acc[4];
                    {   // phase 1: bias + slots 8..14 (weights q4..q7 register-cached)
                        ulonglong2 w4 = sw[l][co][4];
                        ulonglong2 w5 = sw[l][co][5];
                        ulonglong2 w6 = sw[l][co][6];
                        ulonglong2 w7 = sw[l][co][7];
#pragma unroll
                        for (int tt = 0; tt < CL; tt++) {
                            const int t = c0 + tt;
                            u64 a = w7.y;                       // bias (slot 15)
                            a = fma2(s[2][t + 2], w4.x, a);     // slot 8
                            a = fma2(s[3][t + 0], w4.y, a);     // slot 9
                            a = fma2(s[3][t + 1], w5.x, a);     // slot 10
                            a = fma2(s[3][t + 2], w5.y, a);     // slot 11
                            a = fma2(s[4][t + 0], w6.x, a);     // slot 12
                            a = fma2(s[4][t + 1], w6.y, a);     // slot 13
                            a = fma2(s[4][t + 2], w7.x, a);     // slot 14
                            acc[tt] = a;
                        }
                    }
                    {   // phase 2: slots 0..7 (weights q0..q3 register-cached)
                        ulonglong2 w0 = sw[l][co][0];
                        ulonglong2 w1 = sw[l][co][1];
                        ulonglong2 w2 = sw[l][co][2];
                        ulonglong2 w3 = sw[l][co][3];
#pragma unroll
                        for (int tt = 0; tt < CL; tt++) {
                            const int t = c0 + tt;
                            u64 a = acc[tt];
                            a = fma2(s[0][t + 0], w0.x, a);     // slot 0
                            a = fma2(s[0][t + 1], w0.y, a);     // slot 1
                            a = fma2(s[0][t + 2], w1.x, a);     // slot 2
                            a = fma2(s[1][t + 0], w1.y, a);     // slot 3
                            a = fma2(s[1][t + 1], w2.x, a);     // slot 4
                            a = fma2(s[1][t + 2], w2.y, a);     // slot 5
                            a = fma2(s[2][t + 0], w3.x, a);     // slot 6
                            a = fma2(s[2][t + 1], w3.y, a);     // slot 7
                            out[co][tt] = relu2(a);
                        }
                    }
                }
            }
            // writeback after the full co sweep (next chunk reads positions >= c0+4 only)
#pragma unroll
            for (int co = 0; co < 5; co++)
                if (co < nco)
#pragma unroll
                    for (int tt = 0; tt < CL; tt++)
                        s[co][c0 + tt] = out[co][tt];
        }
    }

    // layer-6 outputs sit at s[0][0], s[0][1]
    const u64 HALF2 = 0x3F0000003F000000ULL;  // {0.5f, 0.5f}
    return mul2(add2(s[0][0], s[0][1]), HALF2);
}

// ---------------- kernels ----------------
__global__ void __launch_bounds__(128) transpose_kernel(const float* __restrict__ x,
                                                        float* __restrict__ zt) {
    int n  = blockIdx.x * blockDim.x + threadIdx.x;
    int bp = blockIdx.y;  // batch pair 0..31
    if (n >= NN) return;
    float lo = x[(size_t)(2 * bp) * NN + n];
    float hi = x[(size_t)(2 * bp + 1) * NN + n];
    *(float2*)(zt + (size_t)n * BB + 2 * bp) = make_float2(lo, hi);
}

__global__ void clear_flags_kernel(unsigned char* f, int* cnt) {
    int i = blockIdx.x * blockDim.x + threadIdx.x;
    if (i < NN) f[i] = 0;
    if (i == 0) *cnt = 0;
}

__global__ void mark_flags_kernel(const int* __restrict__ drv,
                                  const int* __restrict__ nbr,
                                  unsigned char* f) {
    int i = blockIdx.x * blockDim.x + threadIdx.x;
    if (i < NDRVN * DD) {
        int d = drv[i >> 4];
        f[nbr[d * DD + (i & 15)]] = 1;
    }
}

__global__ void compact_kernel(const unsigned char* __restrict__ f,
                               int* __restrict__ list, int* __restrict__ cnt) {
    int i = blockIdx.x * blockDim.x + threadIdx.x;
    if (i < NN && f[i]) {
        int pos = atomicAdd(cnt, 1);
        list[pos] = i;
    }
}

__global__ void __launch_bounds__(128) pass_kernel(const float* __restrict__ zin,
                                                   float* __restrict__ zout,
                                                   const int* __restrict__ nbr,
                                                   Params p) {
    __shared__ ulonglong2 s_w[7][5][8];
    load_weights(p, s_w);
    int warp = threadIdx.x >> 5;
    int lane = threadIdx.x & 31;
    int node = blockIdx.x * 4 + warp;
    if (node >= NN) return;
    u64 r = node_forward(zin, nbr + node * DD, lane, s_w);
    *(u64*)(zout + (size_t)node * BB + 2 * lane) = r;
}

__global__ void __launch_bounds__(128) pass_list_kernel(const float* __restrict__ zin,
                                                        float* __restrict__ zout,
                                                        const int* __restrict__ nbr,
                                                        const int* __restrict__ list,
                                                        const int* __restrict__ cnt,
                                                        Params p) {
    __shared__ ulonglong2 s_w[7][5][8];
    load_weights(p, s_w);
    int warp = threadIdx.x >> 5;
    int lane = threadIdx.x & 31;
    int i = blockIdx.x * 4 + warp;
    if (i >= *cnt) return;
    int node = list[i];
    u64 r = node_forward(zin, nbr + node * DD, lane, s_w);
    *(u64*)(zout + (size_t)node * BB + 2 * lane) = r;
}

__global__ void __launch_bounds__(128) driver_kernel(const float* __restrict__ zin,
                                                     const int* __restrict__ nbr,
                                                     const int* __restrict__ drv,
                                                     float* __restrict__ out,
                                                     Params p) {
    __shared__ ulonglong2 s_w[7][5][8];
    load_weights(p, s_w);
    int warp = threadIdx.x >> 5;
    int lane = threadIdx.x & 31;
    int i = blockIdx.x * 4 + warp;
    if (i >= NDRVN) return;
    int node = drv[i];
    u64 r = node_forward(zin, nbr + node * DD, lane, s_w);
    float lo, hi;
    asm("mov.b64 {%0, %1}, %2;" : "=f"(lo), "=f"(hi) : "l"(r));
    out[(size_t)(2 * lane) * NDRVN + i]     = lo;
    out[(size_t)(2 * lane + 1) * NDRVN + i] = hi;
}

// ---------------- launch ----------------
extern "C" void kernel_launch(void* const* d_in, const int* in_sizes, int n_in,
                              void* d_out, int out_size) {
    const float* x   = (const float*)d_in[0];
    const int*   nbr = (const int*)d_in[1];
    const int*   drv = (const int*)d_in[2];
    Params p;
    for (int l = 0; l < 7; l++) {
        p.w[l] = (const float*)d_in[3 + 2 * l];
        p.b[l] = (const float*)d_in[4 + 2 * l];
    }

    float* A; float* B; unsigned char* fl; int* lst; int* cnt;
    cudaGetSymbolAddress((void**)&A,   g_bufA);
    cudaGetSymbolAddress((void**)&B,   g_bufB);
    cudaGetSymbolAddress((void**)&fl,  g_flags);
    cudaGetSymbolAddress((void**)&lst, g_list);
    cudaGetSymbolAddress((void**)&cnt, g_cnt);

    const int blocks_full = (NN + 3) / 4;
    const int blocks_list = (MAXACT + 3) / 4;

    // transpose z0 to (N, B)
    transpose_kernel<<<dim3((NN + 127) / 128, BB / 2), 128>>>(x, A);
    // active-set flags for pass 3
    clear_flags_kernel<<<(NN + 255) / 256, 256>>>(fl, cnt);
    mark_flags_kernel<<<(NDRVN * DD + 255) / 256, 256>>>(drv, nbr, fl);
    // pass 1 (full)
    pass_kernel<<<blocks_full, 128>>>(A, B, nbr, p);
    // compact flags into list
    compact_kernel<<<(NN + 255) / 256, 256>>>(fl, lst, cnt);
    // pass 2 (full)
    pass_kernel<<<blocks_full, 128>>>(B, A, nbr, p);
    // pass 3 (compacted active set, <=16000 nodes)
    pass_list_kernel<<<blocks_list, 128>>>(A, B, nbr, lst, cnt, p);
    // pass 4 (drivers only, straight to output)
    driver_kernel<<<(NDRVN + 3) / 4, 128>>>(B, nbr, drv, (float*)d_out, p);
}